// round 2
// baseline (speedup 1.0000x reference)
#include <cuda_runtime.h>
#include <cuda_bf16.h>

// ShadingLayer: out[b,c,h,w] = sum_k L[b,c,k] * H_k(n[b,:,h,w])
// H_k = 9 SH basis functions of the normal (nx,ny,nz), folded into a
// quadratic form per (b,c):
//   out = a0 + ax*nx + ay*ny + az*nz
//       + axx*nx^2 + ayy*ny^2 + azz*nz^2
//       + axy*nx*ny + axz*nx*nz + ayz*ny*nz
//
// SH constants (fp32 of the reference np.float32 values):
//   C1 = pi * 1/sqrt(4pi), C2 = (2pi/3)*sqrt(3/(4pi)),
//   C3 = (pi/4)*0.5*sqrt(5/(4pi)), C4 = (pi/4)*3*sqrt(5/(12pi)),
//   C5 = (pi/4)*3*sqrt(5/(48pi))

#define SH_C1 0.88622692545276f
#define SH_C2 1.02332670794649f
#define SH_C3 0.24770795610038f
#define SH_C4 0.85808553113514f
#define SH_C5 0.42904276556757f

static constexpr int PLANE  = 512 * 512;   // floats per (b, ch) plane
static constexpr int PLANE4 = PLANE / 4;   // float4s per plane = 65536
static constexpr int TPB    = 256;
static constexpr int V      = 2;           // float4s per thread

__global__ __launch_bounds__(TPB) void shading_kernel(
    const float* __restrict__ nrm,   // (64, 3, 512, 512)
    const float* __restrict__ light, // (64, 27)
    float* __restrict__ out)         // (64, 3, 512, 512)
{
    const int b  = blockIdx.y;
    const int i0 = (blockIdx.x * TPB) * V + threadIdx.x;  // first float4 idx

    __shared__ float Ls[27];
    if (threadIdx.x < 27) Ls[threadIdx.x] = light[b * 27 + threadIdx.x];
    __syncthreads();

    // Fold SH constants + light coeffs into 10 quadratic-form coeffs / channel.
    float a0[3], ax[3], ay[3], az[3], axx[3], ayy[3], azz[3], axy[3], axz[3], ayz[3];
    #pragma unroll
    for (int c = 0; c < 3; c++) {
        const float l0 = Ls[c * 9 + 0], l1 = Ls[c * 9 + 1], l2 = Ls[c * 9 + 2];
        const float l3 = Ls[c * 9 + 3], l4 = Ls[c * 9 + 4], l5 = Ls[c * 9 + 5];
        const float l6 = Ls[c * 9 + 6], l7 = Ls[c * 9 + 7], l8 = Ls[c * 9 + 8];
        a0[c]  = l0 * SH_C1;                       // H1
        az[c]  = l1 * SH_C2;                       // H2 = C2*nz
        ax[c]  = l2 * SH_C2;                       // H3 = C2*nx
        ay[c]  = l3 * SH_C2;                       // H4 = C2*ny
        axx[c] = -l4 * SH_C3 + l7 * SH_C5;         // from H5, H8
        ayy[c] = -l4 * SH_C3 - l7 * SH_C5;
        azz[c] = 2.0f * l4 * SH_C3;
        axz[c] = l5 * SH_C4;                       // H6
        ayz[c] = l6 * SH_C4;                       // H7
        axy[c] = l8 * SH_C4;                       // H9
    }

    const size_t base = (size_t)b * 3 * PLANE;
    const float4* __restrict__ pin  = reinterpret_cast<const float4*>(nrm + base);
    float4* __restrict__       pout = reinterpret_cast<float4*>(out + base);

    // Front-batch all 6 loads for max MLP.
    float4 X[V], Y[V], Z[V];
    #pragma unroll
    for (int v = 0; v < V; v++) {
        const int i = i0 + v * TPB;
        X[v] = pin[i];
        Y[v] = pin[PLANE4 + i];
        Z[v] = pin[2 * PLANE4 + i];
    }

    #pragma unroll
    for (int v = 0; v < V; v++) {
        float4 O[3];
        #pragma unroll
        for (int j = 0; j < 4; j++) {
            const float x = (&X[v].x)[j];
            const float y = (&Y[v].x)[j];
            const float z = (&Z[v].x)[j];
            const float xx = x * x, yy = y * y, zz = z * z;
            const float xy = x * y, xz = x * z, yz = y * z;
            #pragma unroll
            for (int c = 0; c < 3; c++) {
                float r = a0[c];
                r = fmaf(ax[c],  x,  r);
                r = fmaf(ay[c],  y,  r);
                r = fmaf(az[c],  z,  r);
                r = fmaf(axx[c], xx, r);
                r = fmaf(ayy[c], yy, r);
                r = fmaf(azz[c], zz, r);
                r = fmaf(axy[c], xy, r);
                r = fmaf(axz[c], xz, r);
                r = fmaf(ayz[c], yz, r);
                (&O[c].x)[j] = r;
            }
        }
        const int i = i0 + v * TPB;
        pout[i]              = O[0];
        pout[PLANE4 + i]     = O[1];
        pout[2 * PLANE4 + i] = O[2];
    }
}

extern "C" void kernel_launch(void* const* d_in, const int* in_sizes, int n_in,
                              void* d_out, int out_size) {
    const float* nrm   = (const float*)d_in[0];   // recnormalch (64,3,512,512)
    const float* light = (const float*)d_in[1];   // fc_light (64,27)
    float* out         = (float*)d_out;

    dim3 grid(PLANE4 / (TPB * V), 64);   // (128, 64)
    shading_kernel<<<grid, TPB>>>(nrm, light, out);
}